// round 3
// baseline (speedup 1.0000x reference)
#include <cuda_runtime.h>
#include <stdint.h>

// samx_qkv_1bit: suffix-automaton retrieval, 1024 independent serial rows.
// R2: single 64-bit state record {tr0:13, tr1:13, f:13, m:12, r+1:12} in smem
//     -> one LDS.64 per walk node (was 2-3 LDS + global rr load).
//     vpk also in smem -> zero global loads on the per-step critical path.
// 7 rows/block * (32KB records + 256B vpk) = 231168 B smem, 147 blocks = 1 wave.

#define BB 4
#define TT 2048
#define CC 256
#define NROWS (BB*CC)          // 1024
#define WPB (TT/32)            // 64 packed words per row
#define STATES 4096            // SAM has <= 2n-1 = 4095 states
#define RPB 7                  // rows (warps) per block

#define F_SHIFT 26
#define M_SHIFT 39
#define R_SHIFT 51
#define ID_MASK 0x1FFFull      // 13-bit state id / transition, 0x1FFF = absent/-1
#define M_MASK  0xFFFull
#define ABSENT  0x1FFF

__device__ uint32_t g_qpack[NROWS*WPB];
__device__ uint32_t g_kpack[NROWS*WPB];
__device__ uint32_t g_vpack[NROWS*WPB];

// ---------------------------------------------------------------------------
// Pack kernel: binarize q,k,v into per-row bitstreams. Coalesced over c.
// ---------------------------------------------------------------------------
__global__ void samx_pack_kernel(const float* __restrict__ q,
                                 const float* __restrict__ k,
                                 const float* __restrict__ v) {
    int c  = threadIdx.x;
    int wi = blockIdx.x;
    int b  = blockIdx.y;
    int row = b * CC + c;
    size_t base = ((size_t)b * TT + (size_t)wi * 32) * CC + c;
    uint32_t qw = 0, kw = 0, vw = 0;
#pragma unroll
    for (int s = 0; s < 32; s++) {
        if (q[base + (size_t)s * CC] > 0.f) qw |= 1u << s;
        if (k[base + (size_t)s * CC] > 0.f) kw |= 1u << s;
        if (v[base + (size_t)s * CC] > 0.f) vw |= 1u << s;
    }
    g_qpack[row * WPB + wi] = qw;
    g_kpack[row * WPB + wi] = kw;
    g_vpack[row * WPB + wi] = vw;
}

// ---------------------------------------------------------------------------
// Main SAM kernel: one warp per row, lane 0 active. All state in smem.
// ---------------------------------------------------------------------------
extern "C" __global__ void __launch_bounds__(32*RPB, 1)
samx_sam_kernel(const float* __restrict__ e, float* __restrict__ out) {
    extern __shared__ unsigned long long smem[];
    int warp = threadIdx.x >> 5;
    int lane = threadIdx.x & 31;
    int row  = blockIdx.x * RPB + warp;

    unsigned long long* S = smem + (size_t)warp * STATES;
    uint32_t* vpk_s = (uint32_t*)(smem + (size_t)RPB * STATES) + warp * WPB;

    // cooperative vpk copy (global -> smem), 64 words per row, 2 per lane
    if (row < NROWS) {
        vpk_s[lane]      = g_vpack[row * WPB + lane];
        vpk_s[lane + 32] = g_vpack[row * WPB + lane + 32];
    }
    __syncwarp();
    if (lane != 0 || row >= NROWS) return;

    const uint32_t* qpk = g_qpack + row * WPB;
    const uint32_t* kpk = g_kpack + row * WPB;

    int b = row >> 8;
    int c = row & (CC - 1);
    float ev = e[c];
    float* op = out + (size_t)b * TT * CC + c;

    // root: tr absent, f=-1, m=0, r+1=0
    S[0] = ID_MASK | (ID_MASK << 13) | (ID_MASK << F_SHIFT);

    int g = 0, u = 1, w = 0, h = 0;
    uint32_t qw = 0, kw = 0;

    for (int i = 0; i < TT; i++) {
        if ((i & 31) == 0) { int wi = i >> 5; qw = qpk[wi]; kw = kpk[wi]; }
        int qs = ((qw >> (i & 31)) & 1) ? 13 : 0;
        int ks = ((kw >> (i & 31)) & 1) ? 13 : 0;

        // ---- query: extend match with symbol q via suffix links ----
        int p = w, x = h;
        for (;;) {
            if (p < 0) { p = 0; x = 0; break; }
            unsigned long long rec = S[p];
            int tq = (int)((rec >> qs) & ID_MASK);
            if (tq != ABSENT) { p = tq; x += 1; break; }
            int mp = (int)((rec >> M_SHIFT) & M_MASK);
            if (x > mp) x = mp;
            int f = (int)((rec >> F_SHIFT) & ID_MASK);
            p = (f == ABSENT) ? -1 : f;
        }
        int y = 0;
        if (x > 0) {
            // tightest state with m >= x; its record already holds r
            unsigned long long recv = S[p];
            for (;;) {
                int f = (int)((recv >> F_SHIFT) & ID_MASK);
                if (f == ABSENT) break;
                unsigned long long recf = S[f];
                if ((int)((recf >> M_SHIFT) & M_MASK) >= x) recv = recf;
                else break;
            }
            int idx = (int)(recv >> R_SHIFT);           // r+1 (bits 51..62)
            y = (int)((vpk_s[idx >> 5] >> (idx & 31)) & 1u);
        }
        op[(size_t)i * CC] = y ? ev : -ev;
        w = p; h = x;

        // ---- key: standard SAM extension with symbol k ----
        int j = u++;
        int p2 = g;
        int fj;
        for (;;) {
            if (p2 < 0) { fj = 0; break; }
            unsigned long long t = S[p2];
            int tk = (int)((t >> ks) & ID_MASK);
            if (tk == ABSENT) {
                S[p2] = (t & ~(ID_MASK << ks)) | ((unsigned long long)j << ks);
                int f = (int)((t >> F_SHIFT) & ID_MASK);
                p2 = (f == ABSENT) ? -1 : f;
            } else {
                int d = tk;
                unsigned long long recd = S[d];
                int md = (int)((recd >> M_SHIFT) & M_MASK);
                int mp = (int)((t >> M_SHIFT) & M_MASK);
                if (mp + 1 == md) {
                    fj = d;
                } else {
                    int bc = u++;                      // clone of d with m = mp+1
                    S[bc] = (recd & ~(M_MASK << M_SHIFT))
                          | ((unsigned long long)(mp + 1) << M_SHIFT);
                    S[d]  = (recd & ~(ID_MASK << F_SHIFT))
                          | ((unsigned long long)bc << F_SHIFT);
                    fj = bc;
                    for (;;) {                         // redirect tk==d -> bc
                        unsigned long long t2 = S[p2];
                        if (((t2 >> ks) & ID_MASK) != (unsigned long long)d) break;
                        S[p2] = (t2 & ~(ID_MASK << ks))
                              | ((unsigned long long)bc << ks);
                        int f = (int)((t2 >> F_SHIFT) & ID_MASK);
                        if (f == ABSENT) break;
                        p2 = f;
                    }
                }
                break;
            }
        }
        // new state j: tr absent, f=fj, m=i+1, r+1=0 (set by propagation below)
        S[j] = ID_MASK | (ID_MASK << 13)
             | ((unsigned long long)fj << F_SHIFT)
             | ((unsigned long long)(i + 1) << M_SHIFT);
        g = j;

        // ---- propagate last end position up the suffix chain ----
        unsigned long long rset = ((unsigned long long)(i + 1)) << R_SHIFT; // r+1 = i+1
        int vst = j;
        for (;;) {
            unsigned long long rec = S[vst];
            S[vst] = (rec & ~(M_MASK << R_SHIFT)) | rset;
            int f = (int)((rec >> F_SHIFT) & ID_MASK);
            if (f == ABSENT) break;
            vst = f;
        }
    }
}

extern "C" void kernel_launch(void* const* d_in, const int* in_sizes, int n_in,
                              void* d_out, int out_size) {
    const float* q = (const float*)d_in[0];
    const float* k = (const float*)d_in[1];
    const float* v = (const float*)d_in[2];
    const float* e = (const float*)d_in[3];
    float* out = (float*)d_out;

    dim3 pg(WPB, BB);
    samx_pack_kernel<<<pg, CC>>>(q, k, v);

    size_t smem = (size_t)RPB * STATES * sizeof(unsigned long long)
                + (size_t)RPB * WPB * sizeof(uint32_t);   // 229376 + 1792 = 231168
    cudaFuncSetAttribute(samx_sam_kernel,
                         cudaFuncAttributeMaxDynamicSharedMemorySize, (int)smem);
    int blocks = (NROWS + RPB - 1) / RPB;                 // 147
    samx_sam_kernel<<<blocks, 32 * RPB, smem>>>(e, out);
}